// round 1
// baseline (speedup 1.0000x reference)
#include <cuda_runtime.h>
#include <math.h>

#define QN    4096
#define SRCN  32768
#define CC    128
#define KNN   32
#define EDGES (2*QN*KNN)   /* 262144 */
#define MHID  384

// ---------------- device scratch (static, allocation-free) ----------------
__device__ float g_v[2][SRCN*CC];       // src_feat @ Wv[l]
__device__ float g_qproj[QN*CC];
__device__ float g_Pq[QN*64];           // ctx @ Wr1[l][32:] + br1
__device__ float g_svw[EDGES];
__device__ unsigned char g_mask[EDGES];
__device__ float g_agg[QN*CC];
__device__ float g_obuf[QN*CC];
__device__ float g_hbuf[QN*MHID];
__device__ float g_feat[QN*CC];

__device__ __forceinline__ float gelu_tanh(float x) {
    float x3 = x*x*x;
    float t = tanhf(0.7978845608028654f * (x + 0.044715f*x3));
    return 0.5f*x*(1.0f + t);
}

// ---------------- generic fp32 tiled GEMM: C = act(A@B + bias) + resid ----
// A[M,K] row-major, B[K,N] row-major, C[M,N]. M%64==0, N%64==0, K%16==0.
__global__ __launch_bounds__(256) void gemm_kernel(
    const float* __restrict__ A, const float* __restrict__ B, float* __restrict__ C,
    int M, int N, int K,
    const float* __restrict__ bias, const float* __restrict__ resid, int act)
{
    __shared__ float As[16][64];
    __shared__ float Bs[16][64];
    int tid = threadIdx.x;
    int m0 = blockIdx.y * 64, n0 = blockIdx.x * 64;
    int arow = tid >> 2, acol = (tid & 3) * 4;
    int brow = tid >> 4, bcol = (tid & 15) * 4;
    int tx = tid & 15, ty = tid >> 4;
    float acc[4][4] = {};

    for (int kk = 0; kk < K; kk += 16) {
        float4 av = *(const float4*)&A[(size_t)(m0 + arow)*K + kk + acol];
        float4 bv = *(const float4*)&B[(size_t)(kk + brow)*N + n0 + bcol];
        As[acol+0][arow] = av.x; As[acol+1][arow] = av.y;
        As[acol+2][arow] = av.z; As[acol+3][arow] = av.w;
        *(float4*)&Bs[brow][bcol] = bv;
        __syncthreads();
        #pragma unroll
        for (int k = 0; k < 16; k++) {
            float4 a4 = *(float4*)&As[k][ty*4];
            float4 b4 = *(float4*)&Bs[k][tx*4];
            acc[0][0] = fmaf(a4.x, b4.x, acc[0][0]); acc[0][1] = fmaf(a4.x, b4.y, acc[0][1]);
            acc[0][2] = fmaf(a4.x, b4.z, acc[0][2]); acc[0][3] = fmaf(a4.x, b4.w, acc[0][3]);
            acc[1][0] = fmaf(a4.y, b4.x, acc[1][0]); acc[1][1] = fmaf(a4.y, b4.y, acc[1][1]);
            acc[1][2] = fmaf(a4.y, b4.z, acc[1][2]); acc[1][3] = fmaf(a4.y, b4.w, acc[1][3]);
            acc[2][0] = fmaf(a4.z, b4.x, acc[2][0]); acc[2][1] = fmaf(a4.z, b4.y, acc[2][1]);
            acc[2][2] = fmaf(a4.z, b4.z, acc[2][2]); acc[2][3] = fmaf(a4.z, b4.w, acc[2][3]);
            acc[3][0] = fmaf(a4.w, b4.x, acc[3][0]); acc[3][1] = fmaf(a4.w, b4.y, acc[3][1]);
            acc[3][2] = fmaf(a4.w, b4.z, acc[3][2]); acc[3][3] = fmaf(a4.w, b4.w, acc[3][3]);
        }
        __syncthreads();
    }
    #pragma unroll
    for (int i = 0; i < 4; i++) {
        int row = m0 + ty*4 + i;
        #pragma unroll
        for (int j = 0; j < 4; j++) {
            int col = n0 + tx*4 + j;
            float x = acc[i][j];
            if (bias)  x += bias[col];
            if (act)   x = gelu_tanh(x);
            if (resid) x += resid[(size_t)row*N + col];
            C[(size_t)row*N + col] = x;
        }
    }
}

// ---------------- per-edge MLP -> svw scalar + mask ----------------------
// hidden = gelu(bess@Wr1[:32] + Pq[dst]); w = hidden@Wr2 + br2; svw = sh . w
__global__ __launch_bounds__(256, 2) void svw_kernel(
    const float* __restrict__ qpos, const float* __restrict__ spos,
    const float* __restrict__ Wr1, const float* __restrict__ Wr2,
    const float* __restrict__ br2,
    const int* __restrict__ esrc, const int* __restrict__ edst,
    const int* __restrict__ escale, int layer)
{
    const float* W1l = Wr1 + layer*96*64;
    const float* W2l = Wr2 + layer*64*9;
    const float* b2l = br2 + layer*9;
    int lane  = threadIdx.x & 31;
    int gwarp = (blockIdx.x*blockDim.x + threadIdx.x) >> 5;
    int nwarp = (gridDim.x*blockDim.x) >> 5;

    // register-cached weights (loop-invariant over edges)
    float Wa[32], Wb[32];
    #pragma unroll
    for (int k = 0; k < 32; k++) {
        Wa[k] = W1l[k*64 + lane];
        Wb[k] = W1l[k*64 + 32 + lane];
    }
    float w2a[9], w2b[9], b2[9];
    #pragma unroll
    for (int i = 0; i < 9; i++) {
        w2a[i] = W2l[lane*9 + i];
        w2b[i] = W2l[(lane+32)*9 + i];
        b2[i]  = b2l[i];
    }

    for (int e = gwarp; e < EDGES; e += nwarp) {
        int src = esrc[e];
        int dst = edst[e];
        int sc  = escale[e];
        float cut = sc ? 0.2f : 0.1f;
        float dx = qpos[dst*3+0] - spos[src*3+0];
        float dy = qpos[dst*3+1] - spos[src*3+1];
        float dz = qpos[dst*3+2] - spos[src*3+2];
        // mask: bit-exact replica of numpy ((q-s)**2).sum(-1) < cut**2
        float d2 = __fadd_rn(__fadd_rn(__fmul_rn(dx,dx), __fmul_rn(dy,dy)), __fmul_rn(dz,dz));
        float rc2 = __fmul_rn(cut, cut);

        float r = sqrtf(d2 + 1e-12f);
        float inv_r = 1.0f / r;
        float ux = dx*inv_r, uy = dy*inv_r, uz = dz*inv_r;
        float sh[9];
        sh[0] = 1.0f; sh[1] = ux; sh[2] = uy; sh[3] = uz;
        sh[4] = ux*uy; sh[5] = uy*uz; sh[6] = uz*uz - (1.0f/3.0f);
        sh[7] = ux*uz; sh[8] = ux*ux - uy*uy;

        float x = 3.14159274f * r / cut;
        float s1, c1;
        sincosf(x, &s1, &c1);
        float norm = sqrtf(2.0f/cut) * inv_r;

        int dbase = dst*64;
        float h0 = g_Pq[dbase + lane];
        float h1 = g_Pq[dbase + 32 + lane];
        float s = s1, c = c1;
        #pragma unroll
        for (int k = 0; k < 32; k++) {
            float b = norm * s;
            h0 = fmaf(b, Wa[k], h0);
            h1 = fmaf(b, Wb[k], h1);
            float ns = fmaf(s, c1,  c*s1);
            float nc = fmaf(c, c1, -s*s1);
            s = ns; c = nc;
        }
        h0 = gelu_tanh(h0);
        h1 = gelu_tanh(h1);

        float t2a = 0.f, t2b = 0.f, sb = 0.f;
        #pragma unroll
        for (int i = 0; i < 9; i++) {
            t2a = fmaf(w2a[i], sh[i], t2a);
            t2b = fmaf(w2b[i], sh[i], t2b);
            sb  = fmaf(b2[i],  sh[i], sb);
        }
        float part = h0*t2a + h1*t2b;
        #pragma unroll
        for (int off = 16; off; off >>= 1)
            part += __shfl_xor_sync(0xffffffffu, part, off);
        if (lane == 0) {
            g_svw[e]  = part + sb;
            g_mask[e] = (d2 < rc2) ? 1 : 0;
        }
    }
}

// ---------------- per-query online-softmax attention ---------------------
// one warp per query; lane owns channels [4*lane, 4*lane+4); head = lane/8
__global__ __launch_bounds__(256) void attn_kernel(const int* __restrict__ esrc, int layer)
{
    int lane = threadIdx.x & 31;
    int q = (blockIdx.x * blockDim.x + threadIdx.x) >> 5;
    if (q >= QN) return;
    const float* vbuf = g_v[layer];

    float4 qv = *(const float4*)&g_qproj[q*CC + lane*4];
    float m = -__int_as_float(0x7f800000);  // -inf
    float d = 0.f, a0 = 0.f, a1 = 0.f, a2 = 0.f, a3 = 0.f;

    for (int j = 0; j < 64; j++) {
        int e = (j < 32) ? (q*KNN + j) : (QN*KNN + q*KNN + (j - 32));
        if (!g_mask[e]) continue;
        int src = esrc[e];
        float w = g_svw[e];
        float4 v4 = *(const float4*)&vbuf[(size_t)src*CC + lane*4];
        float p = qv.x*v4.x + qv.y*v4.y + qv.z*v4.z + qv.w*v4.w;
        p += __shfl_xor_sync(0xffffffffu, p, 1);
        p += __shfl_xor_sync(0xffffffffu, p, 2);
        p += __shfl_xor_sync(0xffffffffu, p, 4);   // full head dot on all 8 lanes
        float z = p * w * 0.17677669529663687f;    // /sqrt(32)
        float logit = (z > 0.f) ? z : 0.2f*z;      // leaky_relu 0.2
        float nm = fmaxf(m, logit);
        float scl = __expf(m - nm);
        float el  = __expf(logit - nm);
        d = d*scl + el;
        float ew = el * w;
        a0 = fmaf(ew, v4.x, a0*scl);
        a1 = fmaf(ew, v4.y, a1*scl);
        a2 = fmaf(ew, v4.z, a2*scl);
        a3 = fmaf(ew, v4.w, a3*scl);
        m = nm;
    }
    float inv = 1.0f / (d + 1e-12f);
    float4 o = make_float4(a0*inv, a1*inv, a2*inv, a3*inv);
    *(float4*)&g_agg[q*CC + lane*4] = o;
}

// ---------------- host orchestration -------------------------------------
extern "C" void kernel_launch(void* const* d_in, const int* in_sizes, int n_in,
                              void* d_out, int out_size)
{
    const float* qpos  = (const float*)d_in[0];
    const float* qfeat = (const float*)d_in[1];
    const float* spos  = (const float*)d_in[2];
    const float* sfeat = (const float*)d_in[3];
    const float* ctx   = (const float*)d_in[4];
    const float* Wq    = (const float*)d_in[5];
    const float* Wv    = (const float*)d_in[6];
    const float* Wo    = (const float*)d_in[7];
    const float* bo    = (const float*)d_in[8];
    const float* Wr1   = (const float*)d_in[9];
    const float* br1   = (const float*)d_in[10];
    const float* Wr2   = (const float*)d_in[11];
    const float* br2   = (const float*)d_in[12];
    const float* Wf1   = (const float*)d_in[13];
    const float* bf1   = (const float*)d_in[14];
    const float* Wf2   = (const float*)d_in[15];
    const float* bf2   = (const float*)d_in[16];
    const int*   esrc  = (const int*)d_in[17];
    const int*   edst  = (const int*)d_in[18];
    const int*   escal = (const int*)d_in[19];
    (void)in_sizes; (void)n_in; (void)out_size;

    float *v_p, *qproj_p, *Pq_p, *agg_p, *obuf_p, *hbuf_p, *feat_p;
    cudaGetSymbolAddress((void**)&v_p,     g_v);
    cudaGetSymbolAddress((void**)&qproj_p, g_qproj);
    cudaGetSymbolAddress((void**)&Pq_p,    g_Pq);
    cudaGetSymbolAddress((void**)&agg_p,   g_agg);
    cudaGetSymbolAddress((void**)&obuf_p,  g_obuf);
    cudaGetSymbolAddress((void**)&hbuf_p,  g_hbuf);
    cudaGetSymbolAddress((void**)&feat_p,  g_feat);

    dim3 thr(256);

    // v[l] = src_feat @ Wv[l]   (layer-static, both upfront)
    for (int l = 0; l < 2; l++)
        gemm_kernel<<<dim3(CC/64, SRCN/64), thr>>>(
            sfeat, Wv + l*CC*CC, v_p + (size_t)l*SRCN*CC,
            SRCN, CC, CC, nullptr, nullptr, 0);

    const float* featin = qfeat;
    for (int l = 0; l < 2; l++) {
        // qproj = feat @ Wq[l]
        gemm_kernel<<<dim3(CC/64, QN/64), thr>>>(
            featin, Wq + l*CC*CC, qproj_p, QN, CC, CC, nullptr, nullptr, 0);
        // Pq = ctx @ Wr1[l][32:, :] + br1[l]
        gemm_kernel<<<dim3(1, QN/64), thr>>>(
            ctx, Wr1 + l*96*64 + 32*64, Pq_p, QN, 64, 64, br1 + l*64, nullptr, 0);
        // per-edge svw + mask
        svw_kernel<<<2048, 256>>>(qpos, spos, Wr1, Wr2, br2, esrc, edst, escal, l);
        // per-query attention -> agg
        attn_kernel<<<QN/8, 256>>>(esrc, l);
        // out = agg @ Wo + bo + feat
        gemm_kernel<<<dim3(CC/64, QN/64), thr>>>(
            agg_p, Wo + l*CC*CC, obuf_p, QN, CC, CC, bo + l*CC, featin, 0);
        // h = gelu(out @ Wf1 + bf1)
        gemm_kernel<<<dim3(MHID/64, QN/64), thr>>>(
            obuf_p, Wf1 + l*CC*MHID, hbuf_p, QN, MHID, CC, bf1 + l*MHID, nullptr, 1);
        // feat_next = h @ Wf2 + bf2 + out
        float* outp = (l == 0) ? feat_p : (float*)d_out;
        gemm_kernel<<<dim3(CC/64, QN/64), thr>>>(
            hbuf_p, Wf2 + l*MHID*CC, outp, QN, CC, MHID, bf2 + l*CC, obuf_p, 0);
        featin = feat_p;
    }
}

// round 2
// speedup vs baseline: 1.0326x; 1.0326x over previous
#include <cuda_runtime.h>
#include <math.h>

#define QN    4096
#define SRCN  32768
#define CC    128
#define KNN   32
#define EDGES (2*QN*KNN)   /* 262144 */
#define MHID  384

// ---------------- device scratch (static, allocation-free) ----------------
__device__ float g_v[2][SRCN*CC];       // src_feat @ Wv[l]
__device__ float g_qproj[QN*CC];
__device__ float g_Pq[QN*64];           // ctx @ Wr1[l][32:] + br1
__device__ float g_svw[EDGES];
__device__ unsigned char g_mask[EDGES];
__device__ float g_agg[QN*CC];
__device__ float g_obuf[QN*CC];
__device__ float g_hbuf[QN*MHID];
__device__ float g_feat[QN*CC];

__device__ __forceinline__ float gelu_tanh(float x) {
    float x3 = x*x*x;
    float t = tanhf(0.7978845608028654f * (x + 0.044715f*x3));
    return 0.5f*x*(1.0f + t);
}

// ============ big-tile SGEMM: 128x128 block, 8x8/thread, double-buffered ==
// A[M,K], B[K,N] row-major. M%128==0, N%128==0, K%8==0.
// Optional batching over blockIdx.z with strides on B and C.
__global__ __launch_bounds__(256) void gemm128(
    const float* __restrict__ A, const float* __restrict__ B0, float* __restrict__ C0,
    int M, int N, int K,
    const float* __restrict__ bias, const float* __restrict__ resid, int act,
    long long strideB, long long strideC)
{
    const float* B = B0 + (long long)blockIdx.z * strideB;
    float*       C = C0 + (long long)blockIdx.z * strideC;
    __shared__ float As[2][8][128];
    __shared__ float Bs[2][8][128];
    int tid  = threadIdx.x;
    int m0   = blockIdx.y * 128, n0 = blockIdx.x * 128;
    int arow = tid >> 1,  acol = (tid & 1) * 4;
    int brow = tid >> 5,  bcol = (tid & 31) * 4;
    int tx   = tid & 15,  ty   = tid >> 4;
    float acc[8][8] = {};

    const float* Aptr = A + (size_t)(m0 + arow) * K + acol;
    const float* Bptr = B + (size_t)brow * N + n0 + bcol;

    float4 av = *(const float4*)Aptr;
    float4 bv = *(const float4*)Bptr;
    As[0][acol+0][arow] = av.x; As[0][acol+1][arow] = av.y;
    As[0][acol+2][arow] = av.z; As[0][acol+3][arow] = av.w;
    *(float4*)&Bs[0][brow][bcol] = bv;
    __syncthreads();

    int buf = 0;
    for (int kk = 8; kk < K; kk += 8) {
        av = *(const float4*)(Aptr + kk);
        bv = *(const float4*)(Bptr + (size_t)kk * N);
        #pragma unroll
        for (int k = 0; k < 8; k++) {
            float a[8], b[8];
            *(float4*)&a[0] = *(float4*)&As[buf][k][ty*4];
            *(float4*)&a[4] = *(float4*)&As[buf][k][64 + ty*4];
            *(float4*)&b[0] = *(float4*)&Bs[buf][k][tx*4];
            *(float4*)&b[4] = *(float4*)&Bs[buf][k][64 + tx*4];
            #pragma unroll
            for (int i = 0; i < 8; i++)
                #pragma unroll
                for (int j = 0; j < 8; j++)
                    acc[i][j] = fmaf(a[i], b[j], acc[i][j]);
        }
        buf ^= 1;
        As[buf][acol+0][arow] = av.x; As[buf][acol+1][arow] = av.y;
        As[buf][acol+2][arow] = av.z; As[buf][acol+3][arow] = av.w;
        *(float4*)&Bs[buf][brow][bcol] = bv;
        __syncthreads();
    }
    #pragma unroll
    for (int k = 0; k < 8; k++) {
        float a[8], b[8];
        *(float4*)&a[0] = *(float4*)&As[buf][k][ty*4];
        *(float4*)&a[4] = *(float4*)&As[buf][k][64 + ty*4];
        *(float4*)&b[0] = *(float4*)&Bs[buf][k][tx*4];
        *(float4*)&b[4] = *(float4*)&Bs[buf][k][64 + tx*4];
        #pragma unroll
        for (int i = 0; i < 8; i++)
            #pragma unroll
            for (int j = 0; j < 8; j++)
                acc[i][j] = fmaf(a[i], b[j], acc[i][j]);
    }

    #pragma unroll
    for (int i = 0; i < 8; i++) {
        int row = m0 + ((i < 4) ? (ty*4 + i) : (64 + ty*4 + i - 4));
        #pragma unroll
        for (int j = 0; j < 8; j++) {
            int col = n0 + ((j < 4) ? (tx*4 + j) : (64 + tx*4 + j - 4));
            float x = acc[i][j];
            if (bias)  x += bias[col];
            if (act)   x = gelu_tanh(x);
            if (resid) x += resid[(size_t)row*N + col];
            C[(size_t)row*N + col] = x;
        }
    }
}

// ============ 64x64 SGEMM (for N<=128 shapes -> more CTAs) ================
__global__ __launch_bounds__(256) void gemm64(
    const float* __restrict__ A, const float* __restrict__ B, float* __restrict__ C,
    int M, int N, int K,
    const float* __restrict__ bias, const float* __restrict__ resid, int act)
{
    __shared__ float As[16][64];
    __shared__ float Bs[16][64];
    int tid = threadIdx.x;
    int m0 = blockIdx.y * 64, n0 = blockIdx.x * 64;
    int arow = tid >> 2, acol = (tid & 3) * 4;
    int brow = tid >> 4, bcol = (tid & 15) * 4;
    int tx = tid & 15, ty = tid >> 4;
    float acc[4][4] = {};

    for (int kk = 0; kk < K; kk += 16) {
        float4 av = *(const float4*)&A[(size_t)(m0 + arow)*K + kk + acol];
        float4 bv = *(const float4*)&B[(size_t)(kk + brow)*N + n0 + bcol];
        As[acol+0][arow] = av.x; As[acol+1][arow] = av.y;
        As[acol+2][arow] = av.z; As[acol+3][arow] = av.w;
        *(float4*)&Bs[brow][bcol] = bv;
        __syncthreads();
        #pragma unroll
        for (int k = 0; k < 16; k++) {
            float4 a4 = *(float4*)&As[k][ty*4];
            float4 b4 = *(float4*)&Bs[k][tx*4];
            acc[0][0] = fmaf(a4.x, b4.x, acc[0][0]); acc[0][1] = fmaf(a4.x, b4.y, acc[0][1]);
            acc[0][2] = fmaf(a4.x, b4.z, acc[0][2]); acc[0][3] = fmaf(a4.x, b4.w, acc[0][3]);
            acc[1][0] = fmaf(a4.y, b4.x, acc[1][0]); acc[1][1] = fmaf(a4.y, b4.y, acc[1][1]);
            acc[1][2] = fmaf(a4.y, b4.z, acc[1][2]); acc[1][3] = fmaf(a4.y, b4.w, acc[1][3]);
            acc[2][0] = fmaf(a4.z, b4.x, acc[2][0]); acc[2][1] = fmaf(a4.z, b4.y, acc[2][1]);
            acc[2][2] = fmaf(a4.z, b4.z, acc[2][2]); acc[2][3] = fmaf(a4.z, b4.w, acc[2][3]);
            acc[3][0] = fmaf(a4.w, b4.x, acc[3][0]); acc[3][1] = fmaf(a4.w, b4.y, acc[3][1]);
            acc[3][2] = fmaf(a4.w, b4.z, acc[3][2]); acc[3][3] = fmaf(a4.w, b4.w, acc[3][3]);
        }
        __syncthreads();
    }
    #pragma unroll
    for (int i = 0; i < 4; i++) {
        int row = m0 + ty*4 + i;
        #pragma unroll
        for (int j = 0; j < 4; j++) {
            int col = n0 + tx*4 + j;
            float x = acc[i][j];
            if (bias)  x += bias[col];
            if (act)   x = gelu_tanh(x);
            if (resid) x += resid[(size_t)row*N + col];
            C[(size_t)row*N + col] = x;
        }
    }
}

// ---------------- per-edge MLP -> svw scalar + mask ----------------------
__global__ __launch_bounds__(256, 2) void svw_kernel(
    const float* __restrict__ qpos, const float* __restrict__ spos,
    const float* __restrict__ Wr1, const float* __restrict__ Wr2,
    const float* __restrict__ br2,
    const int* __restrict__ esrc, const int* __restrict__ edst,
    const int* __restrict__ escale, int layer)
{
    const float* W1l = Wr1 + layer*96*64;
    const float* W2l = Wr2 + layer*64*9;
    const float* b2l = br2 + layer*9;
    int lane  = threadIdx.x & 31;
    int gwarp = (blockIdx.x*blockDim.x + threadIdx.x) >> 5;
    int nwarp = (gridDim.x*blockDim.x) >> 5;

    float Wa[32], Wb[32];
    #pragma unroll
    for (int k = 0; k < 32; k++) {
        Wa[k] = W1l[k*64 + lane];
        Wb[k] = W1l[k*64 + 32 + lane];
    }
    float w2a[9], w2b[9], b2[9];
    #pragma unroll
    for (int i = 0; i < 9; i++) {
        w2a[i] = W2l[lane*9 + i];
        w2b[i] = W2l[(lane+32)*9 + i];
        b2[i]  = b2l[i];
    }

    for (int e = gwarp; e < EDGES; e += nwarp) {
        int src = esrc[e];
        int dst = edst[e];
        int sc  = escale[e];
        float cut = sc ? 0.2f : 0.1f;
        float dx = qpos[dst*3+0] - spos[src*3+0];
        float dy = qpos[dst*3+1] - spos[src*3+1];
        float dz = qpos[dst*3+2] - spos[src*3+2];
        float d2 = __fadd_rn(__fadd_rn(__fmul_rn(dx,dx), __fmul_rn(dy,dy)), __fmul_rn(dz,dz));
        float rc2 = __fmul_rn(cut, cut);

        float r = sqrtf(d2 + 1e-12f);
        float inv_r = 1.0f / r;
        float ux = dx*inv_r, uy = dy*inv_r, uz = dz*inv_r;
        float sh[9];
        sh[0] = 1.0f; sh[1] = ux; sh[2] = uy; sh[3] = uz;
        sh[4] = ux*uy; sh[5] = uy*uz; sh[6] = uz*uz - (1.0f/3.0f);
        sh[7] = ux*uz; sh[8] = ux*ux - uy*uy;

        float x = 3.14159274f * r / cut;
        float s1, c1;
        sincosf(x, &s1, &c1);
        float norm = sqrtf(2.0f/cut) * inv_r;

        int dbase = dst*64;
        float h0 = g_Pq[dbase + lane];
        float h1 = g_Pq[dbase + 32 + lane];
        float s = s1, c = c1;
        #pragma unroll
        for (int k = 0; k < 32; k++) {
            float b = norm * s;
            h0 = fmaf(b, Wa[k], h0);
            h1 = fmaf(b, Wb[k], h1);
            float ns = fmaf(s, c1,  c*s1);
            float nc = fmaf(c, c1, -s*s1);
            s = ns; c = nc;
        }
        h0 = gelu_tanh(h0);
        h1 = gelu_tanh(h1);

        float t2a = 0.f, t2b = 0.f, sb = 0.f;
        #pragma unroll
        for (int i = 0; i < 9; i++) {
            t2a = fmaf(w2a[i], sh[i], t2a);
            t2b = fmaf(w2b[i], sh[i], t2b);
            sb  = fmaf(b2[i],  sh[i], sb);
        }
        float part = h0*t2a + h1*t2b;
        #pragma unroll
        for (int off = 16; off; off >>= 1)
            part += __shfl_xor_sync(0xffffffffu, part, off);
        if (lane == 0) {
            g_svw[e]  = part + sb;
            g_mask[e] = (d2 < rc2) ? 1 : 0;
        }
    }
}

// ---------------- per-query online-softmax attention ---------------------
__global__ __launch_bounds__(256) void attn_kernel(const int* __restrict__ esrc, int layer)
{
    int lane = threadIdx.x & 31;
    int q = (blockIdx.x * blockDim.x + threadIdx.x) >> 5;
    if (q >= QN) return;
    const float* vbuf = g_v[layer];

    float4 qv = *(const float4*)&g_qproj[q*CC + lane*4];
    float m = -__int_as_float(0x7f800000);
    float d = 0.f, a0 = 0.f, a1 = 0.f, a2 = 0.f, a3 = 0.f;

    for (int j = 0; j < 64; j++) {
        int e = (j < 32) ? (q*KNN + j) : (QN*KNN + q*KNN + (j - 32));
        if (!g_mask[e]) continue;
        int src = esrc[e];
        float w = g_svw[e];
        float4 v4 = *(const float4*)&vbuf[(size_t)src*CC + lane*4];
        float p = qv.x*v4.x + qv.y*v4.y + qv.z*v4.z + qv.w*v4.w;
        p += __shfl_xor_sync(0xffffffffu, p, 1);
        p += __shfl_xor_sync(0xffffffffu, p, 2);
        p += __shfl_xor_sync(0xffffffffu, p, 4);
        float z = p * w * 0.17677669529663687f;
        float logit = (z > 0.f) ? z : 0.2f*z;
        float nm = fmaxf(m, logit);
        float scl = __expf(m - nm);
        float el  = __expf(logit - nm);
        d = d*scl + el;
        float ew = el * w;
        a0 = fmaf(ew, v4.x, a0*scl);
        a1 = fmaf(ew, v4.y, a1*scl);
        a2 = fmaf(ew, v4.z, a2*scl);
        a3 = fmaf(ew, v4.w, a3*scl);
        m = nm;
    }
    float inv = 1.0f / (d + 1e-12f);
    float4 o = make_float4(a0*inv, a1*inv, a2*inv, a3*inv);
    *(float4*)&g_agg[q*CC + lane*4] = o;
}

// ---------------- host orchestration -------------------------------------
extern "C" void kernel_launch(void* const* d_in, const int* in_sizes, int n_in,
                              void* d_out, int out_size)
{
    const float* qpos  = (const float*)d_in[0];
    const float* qfeat = (const float*)d_in[1];
    const float* spos  = (const float*)d_in[2];
    const float* sfeat = (const float*)d_in[3];
    const float* ctx   = (const float*)d_in[4];
    const float* Wq    = (const float*)d_in[5];
    const float* Wv    = (const float*)d_in[6];
    const float* Wo    = (const float*)d_in[7];
    const float* bo    = (const float*)d_in[8];
    const float* Wr1   = (const float*)d_in[9];
    const float* br1   = (const float*)d_in[10];
    const float* Wr2   = (const float*)d_in[11];
    const float* br2   = (const float*)d_in[12];
    const float* Wf1   = (const float*)d_in[13];
    const float* bf1   = (const float*)d_in[14];
    const float* Wf2   = (const float*)d_in[15];
    const float* bf2   = (const float*)d_in[16];
    const int*   esrc  = (const int*)d_in[17];
    const int*   edst  = (const int*)d_in[18];
    const int*   escal = (const int*)d_in[19];
    (void)in_sizes; (void)n_in; (void)out_size;

    float *v_p, *qproj_p, *Pq_p, *agg_p, *obuf_p, *hbuf_p, *feat_p;
    cudaGetSymbolAddress((void**)&v_p,     g_v);
    cudaGetSymbolAddress((void**)&qproj_p, g_qproj);
    cudaGetSymbolAddress((void**)&Pq_p,    g_Pq);
    cudaGetSymbolAddress((void**)&agg_p,   g_agg);
    cudaGetSymbolAddress((void**)&obuf_p,  g_obuf);
    cudaGetSymbolAddress((void**)&hbuf_p,  g_hbuf);
    cudaGetSymbolAddress((void**)&feat_p,  g_feat);

    dim3 thr(256);

    // v[l] = src_feat @ Wv[l] for BOTH layers in one batched launch
    gemm128<<<dim3(1, SRCN/128, 2), thr>>>(
        sfeat, Wv, v_p, SRCN, CC, CC, nullptr, nullptr, 0,
        (long long)CC*CC, (long long)SRCN*CC);

    const float* featin = qfeat;
    for (int l = 0; l < 2; l++) {
        // qproj = feat @ Wq[l]       (128 CTAs)
        gemm64<<<dim3(CC/64, QN/64), thr>>>(
            featin, Wq + l*CC*CC, qproj_p, QN, CC, CC, nullptr, nullptr, 0);
        // Pq = ctx @ Wr1[l][32:, :] + br1[l]
        gemm64<<<dim3(1, QN/64), thr>>>(
            ctx, Wr1 + l*96*64 + 32*64, Pq_p, QN, 64, 64, br1 + l*64, nullptr, 0);
        // per-edge svw + mask
        svw_kernel<<<2048, 256>>>(qpos, spos, Wr1, Wr2, br2, esrc, edst, escal, l);
        // per-query attention -> agg
        attn_kernel<<<QN/8, 256>>>(esrc, l);
        // out = agg @ Wo + bo + feat
        gemm64<<<dim3(CC/64, QN/64), thr>>>(
            agg_p, Wo + l*CC*CC, obuf_p, QN, CC, CC, bo + l*CC, featin, 0);
        // h = gelu(out @ Wf1 + bf1)   (N=384 -> 96 big-tile CTAs)
        gemm128<<<dim3(MHID/128, QN/128, 1), thr>>>(
            obuf_p, Wf1 + l*CC*MHID, hbuf_p, QN, MHID, CC, bf1 + l*MHID, nullptr, 1,
            0LL, 0LL);
        // feat_next = h @ Wf2 + bf2 + out
        float* outp = (l == 0) ? feat_p : (float*)d_out;
        gemm64<<<dim3(CC/64, QN/64), thr>>>(
            hbuf_p, Wf2 + l*MHID*CC, outp, QN, CC, MHID, bf2 + l*CC, obuf_p, 0);
        featin = feat_p;
    }
}